// round 2
// baseline (speedup 1.0000x reference)
#include <cuda_runtime.h>

// ---------------------------------------------------------------------------
// Meta-linear: y[b,o] = (1/sqrt(D)) * sum_{i,k} W[o,i,k] x[b,i] x[b,k] + bias[o]
// applied DEPTH=2 times. B=128, D=512, fp32 throughout.
//
// Pass structure (x6 kernel launches, graph-capturable, no allocations):
//   xpose_k   : XT[d][b] = x[b][d]                      (coalesced feeds)
//   meta_main : split-K GEMM, FFMA2 (fma.rn.f32x2) core -> g_part[s][b][o]
//   reduce_k  : y[b][o] = (1/sqrt(D)) * sum_s part + bias
// ---------------------------------------------------------------------------

namespace {
constexpr int D   = 512;
constexpr int NB  = 128;        // batch
constexpr int BN  = 128;        // o-tile per block
constexpr int BK  = 32;         // k-chunk
constexpr int IPB = 2;          // i's per block (split-K granularity)
constexpr int NIB = D / IPB;    // 256 K-slices
constexpr int NOB = D / BN;     // 4 o-tiles
constexpr int WSP = BN + 4;     // padded Ws row (bank-conflict relief, keeps 16B align)
constexpr float INV_SQRT_D = 0.044194173824159216f;  // 1/sqrt(512)
}

__device__ float g_xt[D * NB];                       // transposed activations [d][b]
__device__ float g_y1[NB * D];                       // intermediate after depth 1
__device__ float g_part[(size_t)NIB * NB * D];       // split-K partials [s][b][o]

// ---------------------------------------------------------------------------
__global__ void __launch_bounds__(256) xpose_k(const float* __restrict__ xsrc) {
    const int idx = blockIdx.x * 256 + threadIdx.x;   // over [b][d]
    const float* __restrict__ s = xsrc ? xsrc : g_y1;
    const int b = idx >> 9;
    const int d = idx & (D - 1);
    g_xt[d * NB + b] = s[idx];
}

// ---------------------------------------------------------------------------
__global__ void __launch_bounds__(256) reduce_k(const float* __restrict__ bias,
                                                float* __restrict__ yext) {
    const int idx = blockIdx.x * 256 + threadIdx.x;   // idx = b*D + o
    float acc = 0.f;
    #pragma unroll 8
    for (int s = 0; s < NIB; ++s)
        acc += g_part[(size_t)s * (NB * D) + idx];
    float* __restrict__ y = yext ? yext : g_y1;
    y[idx] = acc * INV_SQRT_D + bias[idx & (D - 1)];
}

// ---------------------------------------------------------------------------
// Block: 256 threads, computes partial[b=0..127][o0..o0+127] over i in [i0,i0+IPB).
// Per-thread micro-tile 8(b) x 8(o), accumulated as 32 packed f32x2 pairs.
__global__ void __launch_bounds__(256, 2) meta_main_k(const float* __restrict__ W) {
    __shared__ float Ws[BK][WSP];   // Ws[k][o] = W[o0+o, i, k0+k]
    __shared__ float As[BK][NB];    // As[k][b] = x[b,i] * x[b,k0+k]
    __shared__ float xis[NB];       // x[b,i]

    const int tid = threadIdx.x;
    const int o0  = blockIdx.x * BN;
    const int i0  = blockIdx.y * IPB;

    const int col = tid & 15;       // o-frag base = col*8
    const int row = tid >> 4;       // b-frag base = row*8

    const int w_kq = tid & 7;       // W loader: k-quad
    const int w_oo = tid >> 3;      // W loader: o (0..31, x4 phases)
    const int a_k  = tid >> 5;      // A loader: k (0..7, x4 phases)
    const int a_b  = (tid & 31) << 2;

    unsigned long long acc[8][4];   // [m(b)][n(o-pair)]
    #pragma unroll
    for (int m = 0; m < 8; ++m)
        #pragma unroll
        for (int n = 0; n < 4; ++n) acc[m][n] = 0ULL;

    for (int ii = 0; ii < IPB; ++ii) {
        const int i = i0 + ii;
        const float* __restrict__ Wi = W + ((size_t)o0 * D + (size_t)i) * D;

        __syncthreads();                       // prior chunk's compute done
        if (tid < NB) xis[tid] = g_xt[i * NB + tid];

        for (int k0 = 0; k0 < D; k0 += BK) {
            __syncthreads();                   // smem free / xis visible

            // ---- load W tile (transposed into Ws[k][o]) ----
            #pragma unroll
            for (int ph = 0; ph < 4; ++ph) {
                const int o = w_oo + ph * 32;
                const float4 v = *reinterpret_cast<const float4*>(
                    Wi + (size_t)o * (D * D) + (k0 + w_kq * 4));
                Ws[w_kq * 4 + 0][o] = v.x;
                Ws[w_kq * 4 + 1][o] = v.y;
                Ws[w_kq * 4 + 2][o] = v.z;
                Ws[w_kq * 4 + 3][o] = v.w;
            }

            // ---- build A tile: As[k][b] = XT[k0+k][b] * x[b,i] ----
            const float4 sx = *reinterpret_cast<const float4*>(&xis[a_b]);
            #pragma unroll
            for (int ph = 0; ph < 4; ++ph) {
                const int k = a_k + ph * 8;
                float4 v = *reinterpret_cast<const float4*>(&g_xt[(k0 + k) * NB + a_b]);
                v.x *= sx.x; v.y *= sx.y; v.z *= sx.z; v.w *= sx.w;
                *reinterpret_cast<float4*>(&As[k][a_b]) = v;
            }
            __syncthreads();

            // ---- FFMA2 micro-kernel ----
            #pragma unroll 8
            for (int kk = 0; kk < BK; ++kk) {
                const float4 a0 = *reinterpret_cast<const float4*>(&As[kk][row * 8]);
                const float4 a1 = *reinterpret_cast<const float4*>(&As[kk][row * 8 + 4]);
                const ulonglong2 b0 = *reinterpret_cast<const ulonglong2*>(&Ws[kk][col * 8]);
                const ulonglong2 b1 = *reinterpret_cast<const ulonglong2*>(&Ws[kk][col * 8 + 4]);
                const float av[8] = {a0.x, a0.y, a0.z, a0.w, a1.x, a1.y, a1.z, a1.w};
                const unsigned long long bv[4] = {b0.x, b0.y, b1.x, b1.y};
                #pragma unroll
                for (int m = 0; m < 8; ++m) {
                    unsigned long long ad;
                    asm("mov.b64 %0, {%1, %1};" : "=l"(ad) : "r"(__float_as_uint(av[m])));
                    #pragma unroll
                    for (int n = 0; n < 4; ++n)
                        asm("fma.rn.f32x2 %0, %1, %2, %0;"
                            : "+l"(acc[m][n]) : "l"(ad), "l"(bv[n]));
                }
            }
        }
    }

    // ---- epilogue: write split-K partial (deterministic, no atomics) ----
    #pragma unroll
    for (int m = 0; m < 8; ++m) {
        const int b = row * 8 + m;
        float out[8];
        #pragma unroll
        for (int n = 0; n < 4; ++n) {
            unsigned lo, hi;
            asm("mov.b64 {%0, %1}, %2;" : "=r"(lo), "=r"(hi) : "l"(acc[m][n]));
            out[2 * n]     = __uint_as_float(lo);
            out[2 * n + 1] = __uint_as_float(hi);
        }
        const size_t base = ((size_t)blockIdx.y * NB + b) * D + o0 + col * 8;
        *reinterpret_cast<float4*>(&g_part[base]) =
            make_float4(out[0], out[1], out[2], out[3]);
        *reinterpret_cast<float4*>(&g_part[base + 4]) =
            make_float4(out[4], out[5], out[6], out[7]);
    }
}

// ---------------------------------------------------------------------------
extern "C" void kernel_launch(void* const* d_in, const int* in_sizes, int n_in,
                              void* d_out, int out_size) {
    const float* x = nullptr;
    const float* W = nullptr;
    const float* bias = nullptr;
    for (int i = 0; i < n_in; ++i) {
        const long long sz = in_sizes[i];
        if (sz == (long long)D * D * D)      W    = (const float*)d_in[i];
        else if (sz == (long long)NB * D)    x    = (const float*)d_in[i];
        else if (sz == (long long)D)         bias = (const float*)d_in[i];
    }
    float* out = (float*)d_out;

    const dim3 mg(NOB, NIB);
    const int  lin_blocks = (NB * D) / 256;   // 256

    // depth 1: x -> g_y1
    xpose_k<<<lin_blocks, 256>>>(x);
    meta_main_k<<<mg, 256>>>(W);
    reduce_k<<<lin_blocks, 256>>>(bias, nullptr);

    // depth 2: g_y1 -> out
    xpose_k<<<lin_blocks, 256>>>(nullptr);
    meta_main_k<<<mg, 256>>>(W);
    reduce_k<<<lin_blocks, 256>>>(bias, out);
}

// round 5
// speedup vs baseline: 3.7365x; 3.7365x over previous
#include <cuda_runtime.h>
#include <cstdint>

// ---------------------------------------------------------------------------
// Meta-linear, DEPTH=2, B=128, D=512:
//   y[b,o] = (1/sqrt(D)) * sum_{i,k} W[o,i,k] x[b,i] x[b,k] + bias[o]
//
// tcgen05 kind::tf32 SS GEMM with full 3xTF32 error compensation:
//   A (= x (x) x, built on the fly) -> Ah + Al   (tf32 hi/lo)
//   W                               -> Wh + Wl   (tf32 hi/lo)
//   C += Ah*Wh + Al*Wh + Ah*Wl      (Al*Wl dropped, O(2^-24))
// Guarded by arch-feature macros so the plain compute_103 ptxas pass
// compiles empty device bodies (tcgen05 is sm_103a-specific).
// ---------------------------------------------------------------------------

#if defined(__CUDA_ARCH__) && (__CUDA_ARCH__ >= 1000) && \
    (defined(__CUDA_ARCH_FEAT_SM103_ALL) || defined(__CUDA_ARCH_FEAT_SM100_ALL) || \
     defined(__CUDA_ARCH_FEAT_SM101_ALL) || defined(__CUDA_ARCH_SPECIFIC__) ||     \
     defined(__CUDA_ARCH_FAMILY_SPECIFIC__))
#define HAS_TCGEN05 1
#else
#define HAS_TCGEN05 0
#endif

namespace {
constexpr int D  = 512;
constexpr int NB = 128;
constexpr float INV_SQRT_D = 0.044194173824159216f;  // 1/sqrt(512)

constexpr int BN   = 256;                   // o per CTA (MMA N)
constexpr int BK   = 32;                    // k per chunk (4 MMAs of K=8 per term)
constexpr int IPB  = 8;                     // i's per CTA
constexpr int NOB  = D / BN;                // 2
constexpr int NIB  = D / IPB;               // 64 split-K slices
constexpr int NCHUNK = IPB * (D / BK);      // 128 chunks per CTA

// dynamic SMEM layout (bytes; tiles 1024-aligned)
constexpr int SM_TM    = 0;                        // TMEM base ptr
constexpr int SM_MBAR  = 8;                        // 2 mbarriers
constexpr int SM_BH    = 1024;                     // W-hi: 2 x 32KB
constexpr int SM_BL    = SM_BH + 2 * 32 * 1024;    // W-lo: 2 x 32KB
constexpr int SM_AH    = SM_BL + 2 * 32 * 1024;    // A-hi: 2 x 16KB
constexpr int SM_AL    = SM_AH + 2 * 16 * 1024;    // A-lo: 2 x 16KB
constexpr int SM_TOTAL = SM_AL + 2 * 16 * 1024;    // 197632 B

// idesc: dtype=F32(1)<<4 | atype=TF32(2)<<7 | btype=TF32(2)<<10 | (N/8)<<17 | (M/16)<<24
constexpr uint32_t IDESC =
    (1u << 4) | (2u << 7) | (2u << 10) | ((BN / 8) << 17) | ((NB / 16) << 24);
}

__device__ float g_y1[NB * D];                     // inter-depth activations
__device__ float g_part[(size_t)NIB * NB * D];     // split-K partials [slice][b][o]

// ===========================================================================
#if HAS_TCGEN05
__device__ __forceinline__ uint32_t smem_u32(const void* p) {
    uint32_t a;
    asm("{ .reg .u64 t; cvta.to.shared.u64 t, %1; cvt.u32.u64 %0, t; }" : "=r"(a) : "l"(p));
    return a;
}
__device__ __forceinline__ uint32_t sw128(uint32_t off) { return off ^ ((off >> 3) & 0x70); }
__device__ __forceinline__ uint64_t sdesc(uint32_t addr) {      // K-major SW128
    return (2ULL << 61) | (1ULL << 46) | (64ULL << 32) | (1ULL << 16)
         | ((uint64_t)(addr >> 4) & 0x3FFF);
}
__device__ __forceinline__ float to_tf32(float v) {
    float r;
    asm("cvt.rna.tf32.f32 %0, %1;" : "=f"(r) : "f"(v));
    return r;
}
__device__ __forceinline__ void mbar_init(uint32_t a, uint32_t cnt) {
    asm volatile("mbarrier.init.shared.b64 [%0], %1;" :: "r"(a), "r"(cnt) : "memory");
}
__device__ __forceinline__ void mbar_wait(uint32_t a, uint32_t parity) {
    uint32_t done;
    asm volatile(
        "{\n\t.reg .pred p;\n\t"
        "mbarrier.try_wait.parity.acquire.cta.shared::cta.b64 p, [%1], %2;\n\t"
        "selp.b32 %0, 1, 0, p;\n\t}"
        : "=r"(done) : "r"(a), "r"(parity) : "memory");
    if (!done) {
        asm volatile(
            "{\n\t.reg .pred P1;\n\t"
            "W_%=:\n\t"
            "mbarrier.try_wait.parity.acquire.cta.shared::cta.b64 P1, [%0], %1, 0x989680;\n\t"
            "@P1 bra.uni DN_%=;\n\t"
            "bra.uni W_%=;\n\t"
            "DN_%=:\n\t}"
            :: "r"(a), "r"(parity) : "memory");
    }
}
__device__ __forceinline__ void tmem_alloc(uint32_t smem_dst, uint32_t ncols) {
    asm volatile("tcgen05.alloc.cta_group::1.sync.aligned.shared::cta.b32 [%0], %1;"
                 :: "r"(smem_dst), "r"(ncols) : "memory");
}
__device__ __forceinline__ void tmem_dealloc(uint32_t tmem, uint32_t ncols) {
    asm volatile("tcgen05.relinquish_alloc_permit.cta_group::1.sync.aligned;");
    asm volatile("tcgen05.dealloc.cta_group::1.sync.aligned.b32 %0, %1;" :: "r"(tmem), "r"(ncols));
}
__device__ __forceinline__ void mma_tf32_ss(uint32_t d, uint64_t ad, uint64_t bd,
                                            uint32_t idesc, uint32_t acc) {
    asm volatile(
        "{\n\t.reg .pred p;\n\t"
        "setp.ne.u32 p, %4, 0;\n\t"
        "tcgen05.mma.cta_group::1.kind::tf32 [%0], %1, %2, %3, {%5, %5, %5, %5}, p;\n\t}"
        :: "r"(d), "l"(ad), "l"(bd), "r"(idesc), "r"(acc), "r"(0u) : "memory");
}
__device__ __forceinline__ void mma_commit(uint32_t mbar) {
    asm volatile(
        "tcgen05.commit.cta_group::1.mbarrier::arrive::one.shared::cluster.b64 [%0];"
        :: "r"(mbar) : "memory");
}
#endif  // HAS_TCGEN05

// ===========================================================================
// Main tensor kernel: one CTA = o-tile(256) x i-slice(8 i's).
// ===========================================================================
__global__ void __launch_bounds__(256, 1)
meta_tc_k(const float* __restrict__ x, const float* __restrict__ W) {
#if HAS_TCGEN05
    extern __shared__ char smem[];
    const uint32_t sb  = smem_u32(smem);
    const int tid  = threadIdx.x;
    const int wid  = tid >> 5;
    const int lane = tid & 31;
    const int o0   = blockIdx.x * BN;
    const int i0   = blockIdx.y * IPB;

    if (tid == 0) {
        mbar_init(sb + SM_MBAR + 0, 1);
        mbar_init(sb + SM_MBAR + 8, 1);
    }
    if (wid == 0) tmem_alloc(sb + SM_TM, 256);
    __syncthreads();
    uint32_t tmem;
    asm volatile("ld.shared.b32 %0, [%1];" : "=r"(tmem) : "r"(sb + SM_TM));

    const int b_row0 = tid >> 3;          // W loader: base o-row (0..31), +32 per j
    const int b_seg  = tid & 7;           // W loader: 16B segment within 128B row
    const int a_b    = tid >> 1;          // A loader: batch row
    const int a_kb   = (tid & 1) * 16;    // A loader: k-half within chunk

    float4 pf[8];
    {   // prologue prefetch: chunk 0 (i = i0, k0 = 0)
        const float* Wi = W + (size_t)o0 * D * D + (size_t)i0 * D;
        #pragma unroll
        for (int j = 0; j < 8; ++j)
            pf[j] = *reinterpret_cast<const float4*>(
                Wi + (size_t)(b_row0 + j * 32) * (D * D) + b_seg * 4);
    }

    int phase[2] = {0, 0};

    for (int c = 0; c < NCHUNK; ++c) {
        const int s = c & 1;
        if (c >= 2) {                      // buffer s free once MMA(c-2) committed
            mbar_wait(sb + SM_MBAR + s * 8, phase[s]);
            phase[s] ^= 1;
        }

        const int i  = i0 + (c >> 4);
        const int k0 = (c & 15) << 5;

        {   // ---- store W tile as tf32 hi/lo (swizzled) ----
            char* bh = smem + SM_BH + s * (32 * 1024);
            char* bl = smem + SM_BL + s * (32 * 1024);
            #pragma unroll
            for (int j = 0; j < 8; ++j) {
                const float4 v = pf[j];
                float4 hi, lo;
                hi.x = to_tf32(v.x); lo.x = to_tf32(v.x - hi.x);
                hi.y = to_tf32(v.y); lo.y = to_tf32(v.y - hi.y);
                hi.z = to_tf32(v.z); lo.z = to_tf32(v.z - hi.z);
                hi.w = to_tf32(v.w); lo.w = to_tf32(v.w - hi.w);
                const uint32_t off =
                    sw128((uint32_t)(b_row0 + j * 32) * 128 + b_seg * 16);
                *reinterpret_cast<float4*>(bh + off) = hi;
                *reinterpret_cast<float4*>(bl + off) = lo;
            }
        }

        {   // ---- A hi/lo tiles: A[b][kk] = x[b,i] * x[b,k0+kk] ----
            const float xi = __ldg(x + a_b * D + i);
            char* ah = smem + SM_AH + s * (16 * 1024);
            char* al = smem + SM_AL + s * (16 * 1024);
            #pragma unroll
            for (int j = 0; j < 4; ++j) {
                const float4 xv = *reinterpret_cast<const float4*>(
                    x + a_b * D + k0 + a_kb + j * 4);
                float4 hi, lo;
                float p;
                p = xi * xv.x; hi.x = to_tf32(p); lo.x = to_tf32(p - hi.x);
                p = xi * xv.y; hi.y = to_tf32(p); lo.y = to_tf32(p - hi.y);
                p = xi * xv.z; hi.z = to_tf32(p); lo.z = to_tf32(p - hi.z);
                p = xi * xv.w; hi.w = to_tf32(p); lo.w = to_tf32(p - hi.w);
                const uint32_t off = sw128((uint32_t)a_b * 128 + a_kb * 4 + j * 16);
                *reinterpret_cast<float4*>(ah + off) = hi;
                *reinterpret_cast<float4*>(al + off) = lo;
            }
        }

        if (c + 1 < NCHUNK) {              // prefetch next W while MMA(c) runs
            const int in  = i0 + ((c + 1) >> 4);
            const int k0n = ((c + 1) & 15) << 5;
            const float* Wi = W + (size_t)o0 * D * D + (size_t)in * D + k0n;
            #pragma unroll
            for (int j = 0; j < 8; ++j)
                pf[j] = *reinterpret_cast<const float4*>(
                    Wi + (size_t)(b_row0 + j * 32) * (D * D) + b_seg * 4);
        }

        __syncthreads();

        if (tid == 0) {
            asm volatile("fence.proxy.async.shared::cta;" ::: "memory");
            const uint64_t bhd = sdesc(sb + SM_BH + s * (32 * 1024));
            const uint64_t bld = sdesc(sb + SM_BL + s * (32 * 1024));
            const uint64_t ahd = sdesc(sb + SM_AH + s * (16 * 1024));
            const uint64_t ald = sdesc(sb + SM_AL + s * (16 * 1024));
            #pragma unroll
            for (int st = 0; st < 4; ++st)          // term 1: Ah * Wh
                mma_tf32_ss(tmem, ahd + st * 2, bhd + st * 2, IDESC,
                            (c > 0 || st > 0) ? 1u : 0u);
            #pragma unroll
            for (int st = 0; st < 4; ++st)          // term 2: Al * Wh
                mma_tf32_ss(tmem, ald + st * 2, bhd + st * 2, IDESC, 1u);
            #pragma unroll
            for (int st = 0; st < 4; ++st)          // term 3: Ah * Wl
                mma_tf32_ss(tmem, ahd + st * 2, bld + st * 2, IDESC, 1u);
            mma_commit(sb + SM_MBAR + s * 8);
        }
    }

    {   // wait for final commit (covers all prior MMAs)
        const int sl = (NCHUNK - 1) & 1;
        mbar_wait(sb + SM_MBAR + sl * 8, phase[sl]);
    }
    asm volatile("tcgen05.fence::after_thread_sync;" ::: "memory");

    if (wid < 4) {
        const int b = wid * 32 + lane;
        #pragma unroll 1
        for (int part = 0; part < 8; ++part) {
            uint32_t r[32];
            asm volatile(
                "tcgen05.ld.sync.aligned.32x32b.x32.b32 "
                "{%0,%1,%2,%3,%4,%5,%6,%7,%8,%9,%10,%11,%12,%13,%14,%15,"
                "%16,%17,%18,%19,%20,%21,%22,%23,%24,%25,%26,%27,%28,%29,%30,%31}, [%32];"
                : "=r"(r[0]), "=r"(r[1]), "=r"(r[2]), "=r"(r[3]), "=r"(r[4]), "=r"(r[5]),
                  "=r"(r[6]), "=r"(r[7]), "=r"(r[8]), "=r"(r[9]), "=r"(r[10]), "=r"(r[11]),
                  "=r"(r[12]), "=r"(r[13]), "=r"(r[14]), "=r"(r[15]), "=r"(r[16]), "=r"(r[17]),
                  "=r"(r[18]), "=r"(r[19]), "=r"(r[20]), "=r"(r[21]), "=r"(r[22]), "=r"(r[23]),
                  "=r"(r[24]), "=r"(r[25]), "=r"(r[26]), "=r"(r[27]), "=r"(r[28]), "=r"(r[29]),
                  "=r"(r[30]), "=r"(r[31])
                : "r"(tmem + part * 32));
            asm volatile("tcgen05.wait::ld.sync.aligned;" ::: "memory");
            float* dst = g_part + ((size_t)blockIdx.y * NB + b) * D + o0 + part * 32;
            #pragma unroll
            for (int q = 0; q < 8; ++q)
                *reinterpret_cast<float4*>(dst + q * 4) = make_float4(
                    __uint_as_float(r[q * 4 + 0]), __uint_as_float(r[q * 4 + 1]),
                    __uint_as_float(r[q * 4 + 2]), __uint_as_float(r[q * 4 + 3]));
        }
    }

    __syncthreads();
    if (wid == 0) tmem_dealloc(tmem, 256);
#endif  // HAS_TCGEN05
}

// ===========================================================================
// Reduce: sums split-K partials, applies 1/sqrt(D) and bias.
// ===========================================================================
__global__ void __launch_bounds__(256) reduce_k(const float* __restrict__ bias,
                                                float* __restrict__ y) {
    const int idx = blockIdx.x * 256 + threadIdx.x;   // idx = b*D + o
    float acc = 0.f;
    #pragma unroll 8
    for (int s = 0; s < NIB; ++s)
        acc += g_part[(size_t)s * (NB * D) + idx];
    y[idx] = acc * INV_SQRT_D + bias[idx & (D - 1)];
}

// ---------------------------------------------------------------------------
extern "C" void kernel_launch(void* const* d_in, const int* in_sizes, int n_in,
                              void* d_out, int out_size) {
    const float* x = nullptr;
    const float* W = nullptr;
    const float* bias = nullptr;
    for (int i = 0; i < n_in; ++i) {
        const long long sz = in_sizes[i];
        if (sz == (long long)D * D * D)   W    = (const float*)d_in[i];
        else if (sz == (long long)NB * D) x    = (const float*)d_in[i];
        else if (sz == (long long)D)      bias = (const float*)d_in[i];
    }
    float* out = (float*)d_out;

    cudaFuncSetAttribute(meta_tc_k, cudaFuncAttributeMaxDynamicSharedMemorySize, SM_TOTAL);

    float* y1;
    cudaGetSymbolAddress((void**)&y1, g_y1);

    const dim3 mg(NOB, NIB);                  // (2, 64)
    const int  lin_blocks = (NB * D) / 256;   // 256

    // depth 1: x -> g_y1
    meta_tc_k<<<mg, 256, SM_TOTAL>>>(x, W);
    reduce_k<<<lin_blocks, 256>>>(bias, y1);

    // depth 2: g_y1 -> out
    meta_tc_k<<<mg, 256, SM_TOTAL>>>(y1, W);
    reduce_k<<<lin_blocks, 256>>>(bias, out);
}

// round 8
// speedup vs baseline: 4.4846x; 1.2002x over previous
#include <cuda_runtime.h>
#include <cstdint>

// ---------------------------------------------------------------------------
// Meta-linear, DEPTH=2, B=128, D=512:
//   y[b,o] = (1/sqrt(D)) * sum_{i,k} W[o,i,k] x[b,i] x[b,k] + bias[o]
//
// tcgen05 kind::f16 (bf16) SS GEMM with 3-term bf16 error compensation:
//   A (= x (x) x, on the fly) -> Ah + Al   (bf16 hi/lo, 16 mantissa bits)
//   W                         -> Wh + Wl   (bf16 hi/lo)
//   C += Ah*Wh + Al*Wh + Ah*Wl             (Al*Wl dropped, ~2^-18.6)
// Grid = 2 o-tiles x 74 i-slices = 148 CTAs (one per SM).
// Arch-feature-macro guarded so the plain compute_103 ptxas pass compiles
// empty device bodies (tcgen05 is sm_103a-specific).
// ---------------------------------------------------------------------------

#if defined(__CUDA_ARCH__) && (__CUDA_ARCH__ >= 1000) && \
    (defined(__CUDA_ARCH_FEAT_SM103_ALL) || defined(__CUDA_ARCH_FEAT_SM100_ALL) || \
     defined(__CUDA_ARCH_FEAT_SM101_ALL) || defined(__CUDA_ARCH_SPECIFIC__) ||     \
     defined(__CUDA_ARCH_FAMILY_SPECIFIC__))
#define HAS_TCGEN05 1
#else
#define HAS_TCGEN05 0
#endif

namespace {
constexpr int D  = 512;
constexpr int NB = 128;
constexpr float INV_SQRT_D = 0.044194173824159216f;  // 1/sqrt(512)

constexpr int BN     = 256;                 // o per CTA (MMA N)
constexpr int BK     = 64;                  // k per chunk (4 MMAs of K=16 per term)
constexpr int NOB    = D / BN;              // 2
constexpr int NSLICE = 74;                  // i-slices (68 x 7i + 6 x 6i = 512)
constexpr int CPI    = D / BK;              // 8 chunks per i

// dynamic SMEM layout (bytes; tiles 1024-aligned)
constexpr int SM_TM    = 0;                        // TMEM base ptr
constexpr int SM_MBAR  = 8;                        // 2 mbarriers
constexpr int SM_BH    = 1024;                     // W-hi (bf16): 2 x 32KB
constexpr int SM_BL    = SM_BH + 2 * 32 * 1024;    // W-lo:        2 x 32KB
constexpr int SM_AH    = SM_BL + 2 * 32 * 1024;    // A-hi:        2 x 16KB
constexpr int SM_AL    = SM_AH + 2 * 16 * 1024;    // A-lo:        2 x 16KB
constexpr int SM_TOTAL = SM_AL + 2 * 16 * 1024;    // 197632 B

// idesc kind::f16: dtype=F32(1)<<4 | atype=BF16(1)<<7 | btype=BF16(1)<<10
//                  | (N/8)<<17 | (M/16)<<24
constexpr uint32_t IDESC =
    (1u << 4) | (1u << 7) | (1u << 10) | ((BN / 8) << 17) | ((NB / 16) << 24);
}

__device__ float g_y1[NB * D];                        // inter-depth activations
__device__ float g_part[(size_t)NSLICE * NB * D];     // split-K partials

// ===========================================================================
#if HAS_TCGEN05
__device__ __forceinline__ uint32_t smem_u32(const void* p) {
    uint32_t a;
    asm("{ .reg .u64 t; cvta.to.shared.u64 t, %1; cvt.u32.u64 %0, t; }" : "=r"(a) : "l"(p));
    return a;
}
__device__ __forceinline__ uint32_t sw128(uint32_t off) { return off ^ ((off >> 3) & 0x70); }
__device__ __forceinline__ uint64_t sdesc(uint32_t addr) {      // K-major SW128
    return (2ULL << 61) | (1ULL << 46) | (64ULL << 32) | (1ULL << 16)
         | ((uint64_t)(addr >> 4) & 0x3FFF);
}
// pack two fp32 -> bf16x2 (a -> low half, b -> high half)
__device__ __forceinline__ uint32_t pack_bf2(float a, float b) {
    uint32_t r;
    asm("cvt.rn.bf16x2.f32 %0, %1, %2;" : "=r"(r) : "f"(b), "f"(a));
    return r;
}
__device__ __forceinline__ float bf_lo(uint32_t r) { return __uint_as_float(r << 16); }
__device__ __forceinline__ float bf_hi(uint32_t r) { return __uint_as_float(r & 0xffff0000u); }

__device__ __forceinline__ void mbar_init(uint32_t a, uint32_t cnt) {
    asm volatile("mbarrier.init.shared.b64 [%0], %1;" :: "r"(a), "r"(cnt) : "memory");
}
__device__ __forceinline__ void mbar_wait(uint32_t a, uint32_t parity) {
    uint32_t done;
    asm volatile(
        "{\n\t.reg .pred p;\n\t"
        "mbarrier.try_wait.parity.acquire.cta.shared::cta.b64 p, [%1], %2;\n\t"
        "selp.b32 %0, 1, 0, p;\n\t}"
        : "=r"(done) : "r"(a), "r"(parity) : "memory");
    if (!done) {
        asm volatile(
            "{\n\t.reg .pred P1;\n\t"
            "W_%=:\n\t"
            "mbarrier.try_wait.parity.acquire.cta.shared::cta.b64 P1, [%0], %1, 0x989680;\n\t"
            "@P1 bra.uni DN_%=;\n\t"
            "bra.uni W_%=;\n\t"
            "DN_%=:\n\t}"
            :: "r"(a), "r"(parity) : "memory");
    }
}
__device__ __forceinline__ void tmem_alloc(uint32_t smem_dst, uint32_t ncols) {
    asm volatile("tcgen05.alloc.cta_group::1.sync.aligned.shared::cta.b32 [%0], %1;"
                 :: "r"(smem_dst), "r"(ncols) : "memory");
}
__device__ __forceinline__ void tmem_dealloc(uint32_t tmem, uint32_t ncols) {
    asm volatile("tcgen05.relinquish_alloc_permit.cta_group::1.sync.aligned;");
    asm volatile("tcgen05.dealloc.cta_group::1.sync.aligned.b32 %0, %1;" :: "r"(tmem), "r"(ncols));
}
__device__ __forceinline__ void mma_bf16_ss(uint32_t d, uint64_t ad, uint64_t bd,
                                            uint32_t idesc, uint32_t acc) {
    asm volatile(
        "{\n\t.reg .pred p;\n\t"
        "setp.ne.u32 p, %4, 0;\n\t"
        "tcgen05.mma.cta_group::1.kind::f16 [%0], %1, %2, %3, {%5, %5, %5, %5}, p;\n\t}"
        :: "r"(d), "l"(ad), "l"(bd), "r"(idesc), "r"(acc), "r"(0u) : "memory");
}
__device__ __forceinline__ void mma_commit(uint32_t mbar) {
    asm volatile(
        "tcgen05.commit.cta_group::1.mbarrier::arrive::one.shared::cluster.b64 [%0];"
        :: "r"(mbar) : "memory");
}
#endif  // HAS_TCGEN05

// ===========================================================================
// Main tensor kernel: one CTA = o-tile(256) x i-slice(6..7 i's).
// ===========================================================================
__global__ void __launch_bounds__(256, 1)
meta_tc_k(const float* __restrict__ x, const float* __restrict__ W) {
#if HAS_TCGEN05
    extern __shared__ char smem[];
    const uint32_t sb  = smem_u32(smem);
    const int tid  = threadIdx.x;
    const int wid  = tid >> 5;
    const int lane = tid & 31;
    const int o0   = blockIdx.x * BN;
    const int sl   = blockIdx.y;
    // non-uniform i-slices: first 68 slices have 7 i's, last 6 have 6.
    const int icnt = (sl < 68) ? 7 : 6;
    const int i0   = (sl < 68) ? sl * 7 : 476 + (sl - 68) * 6;
    const int nchunk = icnt * CPI;

    if (tid == 0) {
        mbar_init(sb + SM_MBAR + 0, 1);
        mbar_init(sb + SM_MBAR + 8, 1);
    }
    if (wid == 0) tmem_alloc(sb + SM_TM, 256);
    __syncthreads();
    uint32_t tmem;
    asm volatile("ld.shared.b32 %0, [%1];" : "=r"(tmem) : "r"(sb + SM_TM));

    // loader geometry
    const int w_r0 = tid >> 4;            // W: base o-row (0..15), +16 per j
    const int w_sg = tid & 15;            // W: 16B fp32 segment (4 k's) in 256B row
    const int a_b  = tid >> 1;            // A: batch row
    const int a_kh = (tid & 1) * 32;      // A: k-half (32 k's) within chunk

    float4 pf[16];
    {   // prologue prefetch: chunk 0 (i = i0, k0 = 0)
        const float* Wi = W + (size_t)o0 * D * D + (size_t)i0 * D;
        #pragma unroll
        for (int j = 0; j < 16; ++j)
            pf[j] = *reinterpret_cast<const float4*>(
                Wi + (size_t)(w_r0 + j * 16) * (D * D) + w_sg * 4);
    }

    int phase[2] = {0, 0};

    for (int c = 0; c < nchunk; ++c) {
        const int s = c & 1;
        if (c >= 2) {                      // buffer s free once MMA(c-2) committed
            mbar_wait(sb + SM_MBAR + s * 8, phase[s]);
            phase[s] ^= 1;
        }

        const int i  = i0 + (c >> 3);
        const int k0 = (c & 7) << 6;

        {   // ---- store W tile as bf16 hi/lo (swizzled, 128B rows) ----
            char* bh = smem + SM_BH + s * (32 * 1024);
            char* bl = smem + SM_BL + s * (32 * 1024);
            #pragma unroll
            for (int j = 0; j < 16; ++j) {
                const float4 v = pf[j];
                const uint32_t h0 = pack_bf2(v.x, v.y);
                const uint32_t h1 = pack_bf2(v.z, v.w);
                const uint32_t l0 = pack_bf2(v.x - bf_lo(h0), v.y - bf_hi(h0));
                const uint32_t l1 = pack_bf2(v.z - bf_lo(h1), v.w - bf_hi(h1));
                const uint32_t off =
                    sw128((uint32_t)(w_r0 + j * 16) * 128 + w_sg * 8);
                *reinterpret_cast<uint2*>(bh + off) = make_uint2(h0, h1);
                *reinterpret_cast<uint2*>(bl + off) = make_uint2(l0, l1);
            }
        }

        {   // ---- A hi/lo tiles: A[b][kk] = x[b,i] * x[b,k0+kk] ----
            const float xi = __ldg(x + a_b * D + i);
            char* ah = smem + SM_AH + s * (16 * 1024);
            char* al = smem + SM_AL + s * (16 * 1024);
            #pragma unroll
            for (int j = 0; j < 8; ++j) {
                const float4 xv = *reinterpret_cast<const float4*>(
                    x + a_b * D + k0 + a_kh + j * 4);
                float4 p;
                p.x = xi * xv.x; p.y = xi * xv.y; p.z = xi * xv.z; p.w = xi * xv.w;
                const uint32_t h0 = pack_bf2(p.x, p.y);
                const uint32_t h1 = pack_bf2(p.z, p.w);
                const uint32_t l0 = pack_bf2(p.x - bf_lo(h0), p.y - bf_hi(h0));
                const uint32_t l1 = pack_bf2(p.z - bf_lo(h1), p.w - bf_hi(h1));
                const uint32_t off =
                    sw128((uint32_t)a_b * 128 + (a_kh + j * 4) * 2);
                *reinterpret_cast<uint2*>(ah + off) = make_uint2(h0, h1);
                *reinterpret_cast<uint2*>(al + off) = make_uint2(l0, l1);
            }
        }

        if (c + 1 < nchunk) {              // prefetch next W while MMA(c) runs
            const int cn  = c + 1;
            const int in  = i0 + (cn >> 3);
            const int k0n = (cn & 7) << 6;
            const float* Wi = W + (size_t)o0 * D * D + (size_t)in * D + k0n;
            #pragma unroll
            for (int j = 0; j < 16; ++j)
                pf[j] = *reinterpret_cast<const float4*>(
                    Wi + (size_t)(w_r0 + j * 16) * (D * D) + w_sg * 4);
        }

        __syncthreads();

        if (tid == 0) {
            asm volatile("fence.proxy.async.shared::cta;" ::: "memory");
            const uint64_t bhd = sdesc(sb + SM_BH + s * (32 * 1024));
            const uint64_t bld = sdesc(sb + SM_BL + s * (32 * 1024));
            const uint64_t ahd = sdesc(sb + SM_AH + s * (16 * 1024));
            const uint64_t ald = sdesc(sb + SM_AL + s * (16 * 1024));
            #pragma unroll
            for (int st = 0; st < 4; ++st)          // term 1: Ah * Wh
                mma_bf16_ss(tmem, ahd + st * 2, bhd + st * 2, IDESC,
                            (c > 0 || st > 0) ? 1u : 0u);
            #pragma unroll
            for (int st = 0; st < 4; ++st)          // term 2: Al * Wh
                mma_bf16_ss(tmem, ald + st * 2, bhd + st * 2, IDESC, 1u);
            #pragma unroll
            for (int st = 0; st < 4; ++st)          // term 3: Ah * Wl
                mma_bf16_ss(tmem, ahd + st * 2, bld + st * 2, IDESC, 1u);
            mma_commit(sb + SM_MBAR + s * 8);
        }
    }

    {   // wait for final commit (covers all prior MMAs)
        const int sf = (nchunk - 1) & 1;
        mbar_wait(sb + SM_MBAR + sf * 8, phase[sf]);
    }
    asm volatile("tcgen05.fence::after_thread_sync;" ::: "memory");

    if (wid < 4) {
        const int b = wid * 32 + lane;
        #pragma unroll 1
        for (int part = 0; part < 8; ++part) {
            uint32_t r[32];
            asm volatile(
                "tcgen05.ld.sync.aligned.32x32b.x32.b32 "
                "{%0,%1,%2,%3,%4,%5,%6,%7,%8,%9,%10,%11,%12,%13,%14,%15,"
                "%16,%17,%18,%19,%20,%21,%22,%23,%24,%25,%26,%27,%28,%29,%30,%31}, [%32];"
                : "=r"(r[0]), "=r"(r[1]), "=r"(r[2]), "=r"(r[3]), "=r"(r[4]), "=r"(r[5]),
                  "=r"(r[6]), "=r"(r[7]), "=r"(r[8]), "=r"(r[9]), "=r"(r[10]), "=r"(r[11]),
                  "=r"(r[12]), "=r"(r[13]), "=r"(r[14]), "=r"(r[15]), "=r"(r[16]), "=r"(r[17]),
                  "=r"(r[18]), "=r"(r[19]), "=r"(r[20]), "=r"(r[21]), "=r"(r[22]), "=r"(r[23]),
                  "=r"(r[24]), "=r"(r[25]), "=r"(r[26]), "=r"(r[27]), "=r"(r[28]), "=r"(r[29]),
                  "=r"(r[30]), "=r"(r[31])
                : "r"(tmem + part * 32));
            asm volatile("tcgen05.wait::ld.sync.aligned;" ::: "memory");
            float* dst = g_part + ((size_t)sl * NB + b) * D + o0 + part * 32;
            #pragma unroll
            for (int q = 0; q < 8; ++q)
                *reinterpret_cast<float4*>(dst + q * 4) = make_float4(
                    __uint_as_float(r[q * 4 + 0]), __uint_as_float(r[q * 4 + 1]),
                    __uint_as_float(r[q * 4 + 2]), __uint_as_float(r[q * 4 + 3]));
        }
    }

    __syncthreads();
    if (wid == 0) tmem_dealloc(tmem, 256);
#endif  // HAS_TCGEN05
}

// ===========================================================================
// Reduce: sums split-K partials (float4), applies 1/sqrt(D) and bias.
// ===========================================================================
__global__ void __launch_bounds__(256) reduce_k(const float* __restrict__ bias,
                                                float* __restrict__ y) {
    const int v = blockIdx.x * 256 + threadIdx.x;     // float4 index over [b][o]
    float4 acc = make_float4(0.f, 0.f, 0.f, 0.f);
    const float4* __restrict__ p =
        reinterpret_cast<const float4*>(g_part) + v;
    #pragma unroll 2
    for (int s = 0; s < NSLICE; ++s) {
        const float4 t = p[(size_t)s * (NB * D / 4)];
        acc.x += t.x; acc.y += t.y; acc.z += t.z; acc.w += t.w;
    }
    const int o4 = (v * 4) & (D - 1);
    const float4 bv = *reinterpret_cast<const float4*>(bias + o4);
    float4 r;
    r.x = acc.x * INV_SQRT_D + bv.x;
    r.y = acc.y * INV_SQRT_D + bv.y;
    r.z = acc.z * INV_SQRT_D + bv.z;
    r.w = acc.w * INV_SQRT_D + bv.w;
    reinterpret_cast<float4*>(y)[v] = r;
}

// ---------------------------------------------------------------------------
extern "C" void kernel_launch(void* const* d_in, const int* in_sizes, int n_in,
                              void* d_out, int out_size) {
    const float* x = nullptr;
    const float* W = nullptr;
    const float* bias = nullptr;
    for (int i = 0; i < n_in; ++i) {
        const long long sz = in_sizes[i];
        if (sz == (long long)D * D * D)   W    = (const float*)d_in[i];
        else if (sz == (long long)NB * D) x    = (const float*)d_in[i];
        else if (sz == (long long)D)      bias = (const float*)d_in[i];
    }
    float* out = (float*)d_out;

    cudaFuncSetAttribute(meta_tc_k, cudaFuncAttributeMaxDynamicSharedMemorySize, SM_TOTAL);

    float* y1;
    cudaGetSymbolAddress((void**)&y1, g_y1);

    const dim3 mg(NOB, NSLICE);                    // (2, 74) = 148 CTAs
    const int  red_blocks = (NB * D) / (256 * 4);  // 64

    // depth 1: x -> g_y1
    meta_tc_k<<<mg, 256, SM_TOTAL>>>(x, W);
    reduce_k<<<red_blocks, 256>>>(bias, y1);

    // depth 2: g_y1 -> out
    meta_tc_k<<<mg, 256, SM_TOTAL>>>(y1, W);
    reduce_k<<<red_blocks, 256>>>(bias, out);
}